// round 1
// baseline (speedup 1.0000x reference)
#include <cuda_runtime.h>

#define H   4096
#define EXP 8
#define NT  1024
#define FULLM 0xFFFFFFFFu

// Reduce 8 per-lane accumulators across 32 lanes via vector-halving butterfly.
// Returns: lane l holds the total for expert e(l) = 4*b4(l) + 2*b3(l) + 1*b2(l)
// (so lane 4e holds expert e). 9 shfls total.
__device__ __forceinline__ float reduce8(float a[8]) {
    const int lane = threadIdx.x & 31;
    // xor16: keep 4 sums
    {
        bool hi = (lane & 16) != 0;
        float s0 = hi ? a[0] : a[4];
        float s1 = hi ? a[1] : a[5];
        float s2 = hi ? a[2] : a[6];
        float s3 = hi ? a[3] : a[7];
        s0 = __shfl_xor_sync(FULLM, s0, 16);
        s1 = __shfl_xor_sync(FULLM, s1, 16);
        s2 = __shfl_xor_sync(FULLM, s2, 16);
        s3 = __shfl_xor_sync(FULLM, s3, 16);
        a[0] = (hi ? a[4] : a[0]) + s0;
        a[1] = (hi ? a[5] : a[1]) + s1;
        a[2] = (hi ? a[6] : a[2]) + s2;
        a[3] = (hi ? a[7] : a[3]) + s3;
    }
    // xor8: keep 2 sums
    {
        bool hi = (lane & 8) != 0;
        float s0 = hi ? a[0] : a[2];
        float s1 = hi ? a[1] : a[3];
        s0 = __shfl_xor_sync(FULLM, s0, 8);
        s1 = __shfl_xor_sync(FULLM, s1, 8);
        a[0] = (hi ? a[2] : a[0]) + s0;
        a[1] = (hi ? a[3] : a[1]) + s1;
    }
    // xor4: keep 1 sum
    {
        bool hi = (lane & 4) != 0;
        float s0 = hi ? a[0] : a[1];
        s0 = __shfl_xor_sync(FULLM, s0, 4);
        a[0] = (hi ? a[1] : a[0]) + s0;
    }
    float v = a[0];
    v += __shfl_xor_sync(FULLM, v, 2);
    v += __shfl_xor_sync(FULLM, v, 1);
    return v;
}

__global__ void __launch_bounds__(NT, 1)
router_kernel(const float* __restrict__ x, const float* __restrict__ W,
              int T, float* __restrict__ out, int flags) {
    __shared__ float partials[2][32][9];  // double-buffered, padded vs bank conflicts

    const int tid  = threadIdx.x;
    const int lane = tid & 31;
    const int warp = tid >> 5;
    const int nb   = gridDim.x;

    // Register-resident W slice: this thread's 4 consecutive k for all 8 experts.
    float4 w[EXP];
#pragma unroll
    for (int e = 0; e < EXP; e++)
        w[e] = *reinterpret_cast<const float4*>(W + e * H + tid * 4);

    const float4* x4 = reinterpret_cast<const float4*>(x);
    const int stride4 = H / 4;

    float* outW = out + (size_t)T * EXP;        // expert_weights [T,2]
    float* outI = out + (size_t)T * (EXP + 2);  // expert_indices [T,2] (as float)

    int r = blockIdx.x;
    float4 xc = make_float4(0.f, 0.f, 0.f, 0.f);
    if (r < T) xc = x4[(size_t)r * stride4 + tid];

    int buf = 0;
    for (; r < T; r += nb, buf ^= 1) {
        // prefetch next row (covers DRAM latency over this row's compute+reduce)
        int rn = r + nb;
        float4 xn = xc;
        if (rn < T) xn = x4[(size_t)rn * stride4 + tid];

        // 32 FMAs: 8 experts x 4 k
        float acc[EXP];
#pragma unroll
        for (int e = 0; e < EXP; e++) {
            float s = xc.x * w[e].x;
            s = fmaf(xc.y, w[e].y, s);
            s = fmaf(xc.z, w[e].z, s);
            s = fmaf(xc.w, w[e].w, s);
            acc[e] = s;
        }

        // intra-warp reduce: lane 4e holds expert e partial
        float v = reduce8(acc);
        if ((lane & 3) == 0)
            partials[buf][warp][lane >> 2] = v;
        __syncthreads();

        // warp 0 finalizes this row while other warps roll into the next iteration
        if (warp == 0) {
            float a2[EXP];
#pragma unroll
            for (int j = 0; j < EXP; j++)
                a2[j] = partials[buf][lane][j];
            float t = reduce8(a2);  // lane 4e -> logit[e]

            // softmax over the 8 distributed logits (orbit over bits {4,3,2})
            float m = t;
            m = fmaxf(m, __shfl_xor_sync(FULLM, m, 16));
            m = fmaxf(m, __shfl_xor_sync(FULLM, m, 8));
            m = fmaxf(m, __shfl_xor_sync(FULLM, m, 4));
            float p = __expf(t - m);
            float s = p;
            s += __shfl_xor_sync(FULLM, s, 16);
            s += __shfl_xor_sync(FULLM, s, 8);
            s += __shfl_xor_sync(FULLM, s, 4);
            float sc = __fdividef(p, s);

            int e = ((lane >> 4) & 1) * 4 + ((lane >> 3) & 1) * 2 + ((lane >> 2) & 1);
            if ((lane & 3) == 0)
                out[(size_t)r * EXP + e] = sc;

            // top-1 argmax (tie -> lower index, matching lax.top_k stability)
            float v1 = sc; int i1 = e;
#pragma unroll
            for (int d = 16; d >= 4; d >>= 1) {
                float ov = __shfl_xor_sync(FULLM, v1, d);
                int   oi = __shfl_xor_sync(FULLM, i1, d);
                if (ov > v1 || (ov == v1 && oi < i1)) { v1 = ov; i1 = oi; }
            }
            // top-2: mask out winner (softmax scores > 0, so -1 is safe)
            float v2 = (e == i1) ? -1.0f : sc; int i2 = e;
#pragma unroll
            for (int d = 16; d >= 4; d >>= 1) {
                float ov = __shfl_xor_sync(FULLM, v2, d);
                int   oi = __shfl_xor_sync(FULLM, i2, d);
                if (ov > v2 || (ov == v2 && oi < i2)) { v2 = ov; i2 = oi; }
            }

            if (lane == 0) {
                if (flags & 1) {
                    outW[(size_t)r * 2 + 0] = v1;
                    outW[(size_t)r * 2 + 1] = v2;
                }
                if (flags & 2) {
                    outI[(size_t)r * 2 + 0] = (float)i1;
                    outI[(size_t)r * 2 + 1] = (float)i2;
                }
            }
        }
        xc = xn;
    }
}

extern "C" void kernel_launch(void* const* d_in, const int* in_sizes, int n_in,
                              void* d_out, int out_size) {
    const float* x = (const float*)d_in[0];
    const float* W = (const float*)d_in[1];
    // d_in[2] is top_k (=2), hardcoded in the kernel structure.

    int T = in_sizes[0] / H;  // 16384

    int dev = 0;
    cudaGetDevice(&dev);
    int sm = 148;
    cudaDeviceGetAttribute(&sm, cudaDevAttrMultiProcessorCount, dev);

    // Guard the optional output regions against a scores-only out buffer.
    int flags = 0;
    if (out_size >= T * (EXP + 2)) flags |= 1;  // weights region present
    if (out_size >= T * (EXP + 4)) flags |= 2;  // indices region present

    router_kernel<<<sm, NT>>>(x, W, T, (float*)d_out, flags);
}

// round 2
// speedup vs baseline: 1.3239x; 1.3239x over previous
#include <cuda_runtime.h>

#define H     4096
#define TMAX  16384
#define EXP   8
#define FULLM 0xFFFFFFFFu

// Phase-1 partials: [row][16 warps][8 experts] = 8 MB
__device__ float g_scratch[(size_t)TMAX * 16 * EXP];

typedef unsigned long long u64;

__device__ __forceinline__ u64 fma2(u64 a, u64 b, u64 c) {
    u64 d; asm("fma.rn.f32x2 %0,%1,%2,%3;" : "=l"(d) : "l"(a), "l"(b), "l"(c)); return d;
}
__device__ __forceinline__ u64 mul2(u64 a, u64 b) {
    u64 d; asm("mul.rn.f32x2 %0,%1,%2;" : "=l"(d) : "l"(a), "l"(b)); return d;
}
__device__ __forceinline__ float hadd2(u64 v) {
    float lo = __uint_as_float((unsigned)v);
    float hi = __uint_as_float((unsigned)(v >> 32));
    return lo + hi;
}

// Reduce 8 per-lane values across 32 lanes (vector-halving butterfly, 9 shfls).
// Result: lane 4e holds the sum for expert e.
__device__ __forceinline__ float reduce8(float a[8]) {
    const int lane = threadIdx.x & 31;
    {
        bool hi = (lane & 16) != 0;
        float s0 = hi ? a[0] : a[4];
        float s1 = hi ? a[1] : a[5];
        float s2 = hi ? a[2] : a[6];
        float s3 = hi ? a[3] : a[7];
        s0 = __shfl_xor_sync(FULLM, s0, 16);
        s1 = __shfl_xor_sync(FULLM, s1, 16);
        s2 = __shfl_xor_sync(FULLM, s2, 16);
        s3 = __shfl_xor_sync(FULLM, s3, 16);
        a[0] = (hi ? a[4] : a[0]) + s0;
        a[1] = (hi ? a[5] : a[1]) + s1;
        a[2] = (hi ? a[6] : a[2]) + s2;
        a[3] = (hi ? a[7] : a[3]) + s3;
    }
    {
        bool hi = (lane & 8) != 0;
        float s0 = hi ? a[0] : a[2];
        float s1 = hi ? a[1] : a[3];
        s0 = __shfl_xor_sync(FULLM, s0, 8);
        s1 = __shfl_xor_sync(FULLM, s1, 8);
        a[0] = (hi ? a[2] : a[0]) + s0;
        a[1] = (hi ? a[3] : a[1]) + s1;
    }
    {
        bool hi = (lane & 4) != 0;
        float s0 = hi ? a[0] : a[1];
        s0 = __shfl_xor_sync(FULLM, s0, 4);
        a[0] = (hi ? a[1] : a[0]) + s0;
    }
    float v = a[0];
    v += __shfl_xor_sync(FULLM, v, 2);
    v += __shfl_xor_sync(FULLM, v, 1);
    return v;
}

// ── Phase 1: streaming GEMV partials. 512 threads; thread owns 8 k
//   (float4 at k=tid*4 and k=2048+tid*4). No block-level sync at all.
__global__ void __launch_bounds__(512, 1)
router_p1(const float* __restrict__ x, const float* __restrict__ W, int T) {
    const int tid  = threadIdx.x;
    const int lane = tid & 31;
    const int warp = tid >> 5;
    const int nb   = gridDim.x;

    // W slice in registers: 8 experts x 2 chunks (each chunk = 2 packed f32x2)
    u64 w0x[EXP], w0y[EXP], w1x[EXP], w1y[EXP];
#pragma unroll
    for (int e = 0; e < EXP; e++) {
        ulonglong2 t0 = reinterpret_cast<const ulonglong2*>(W + e * H)[tid];
        ulonglong2 t1 = reinterpret_cast<const ulonglong2*>(W + e * H)[tid + 512];
        w0x[e] = t0.x; w0y[e] = t0.y;
        w1x[e] = t1.x; w1y[e] = t1.y;
    }

    // software pipeline: cur, +1, +2
    int r = blockIdx.x;
    ulonglong2 ac, bc, an, bn;
    ac = bc = an = bn = make_ulonglong2(0ull, 0ull);
    if (r < T) {
        const ulonglong2* xr = reinterpret_cast<const ulonglong2*>(x + (size_t)r * H);
        ac = xr[tid]; bc = xr[tid + 512];
    }
    if (r + nb < T) {
        const ulonglong2* xr = reinterpret_cast<const ulonglong2*>(x + (size_t)(r + nb) * H);
        an = xr[tid]; bn = xr[tid + 512];
    }

    for (; r < T; r += nb) {
        // prefetch row r + 2*nb
        ulonglong2 ap = an, bp = bn;
        int rp = r + 2 * nb;
        if (rp < T) {
            const ulonglong2* xr = reinterpret_cast<const ulonglong2*>(x + (size_t)rp * H);
            ap = xr[tid]; bp = xr[tid + 512];
        }

        float a8[EXP];
#pragma unroll
        for (int e = 0; e < EXP; e++) {
            u64 acc = mul2(bc.y, w1y[e]);
            acc = fma2(bc.x, w1x[e], acc);
            acc = fma2(ac.y, w0y[e], acc);
            acc = fma2(ac.x, w0x[e], acc);
            a8[e] = hadd2(acc);
        }

        float v = reduce8(a8);
        if ((lane & 3) == 0)
            g_scratch[((size_t)r * 16 + warp) * EXP + (lane >> 2)] = v;

        ac = an; bc = bn;
        an = ap; bn = bp;
    }
}

// ── Phase 2: one warp per row. Reduce 16x8 partials, softmax, top-2, outputs.
__global__ void __launch_bounds__(256)
router_p2(int T, float* __restrict__ out, int flags) {
    const int gw   = (blockIdx.x * 256 + threadIdx.x) >> 5;  // global warp = row
    const int lane = threadIdx.x & 31;
    if (gw >= T) return;
    const int r = gw;

    float a[EXP];
    if (lane < 16) {
        const float4* p = reinterpret_cast<const float4*>(g_scratch + ((size_t)r * 16 + lane) * EXP);
        float4 u = p[0], v = p[1];
        a[0] = u.x; a[1] = u.y; a[2] = u.z; a[3] = u.w;
        a[4] = v.x; a[5] = v.y; a[6] = v.z; a[7] = v.w;
    } else {
#pragma unroll
        for (int j = 0; j < EXP; j++) a[j] = 0.0f;
    }

    float t = reduce8(a);  // lane 4e -> logit[e]

    // softmax over the 8 distributed logits (orbit of lane bits {16,8,4})
    float m = t;
    m = fmaxf(m, __shfl_xor_sync(FULLM, m, 16));
    m = fmaxf(m, __shfl_xor_sync(FULLM, m, 8));
    m = fmaxf(m, __shfl_xor_sync(FULLM, m, 4));
    float p = __expf(t - m);
    float s = p;
    s += __shfl_xor_sync(FULLM, s, 16);
    s += __shfl_xor_sync(FULLM, s, 8);
    s += __shfl_xor_sync(FULLM, s, 4);
    float sc = __fdividef(p, s);

    int e = ((lane >> 4) & 1) * 4 + ((lane >> 3) & 1) * 2 + ((lane >> 2) & 1);
    if ((lane & 3) == 0)
        out[(size_t)r * EXP + e] = sc;

    // top-1 (ties -> lower index, matching lax.top_k)
    float v1 = sc; int i1 = e;
#pragma unroll
    for (int d = 16; d >= 4; d >>= 1) {
        float ov = __shfl_xor_sync(FULLM, v1, d);
        int   oi = __shfl_xor_sync(FULLM, i1, d);
        if (ov > v1 || (ov == v1 && oi < i1)) { v1 = ov; i1 = oi; }
    }
    // top-2: mask winner (softmax scores > 0)
    float v2 = (e == i1) ? -1.0f : sc; int i2 = e;
#pragma unroll
    for (int d = 16; d >= 4; d >>= 1) {
        float ov = __shfl_xor_sync(FULLM, v2, d);
        int   oi = __shfl_xor_sync(FULLM, i2, d);
        if (ov > v2 || (ov == v2 && oi < i2)) { v2 = ov; i2 = oi; }
    }

    if (lane == 0) {
        float* outW = out + (size_t)T * EXP;
        float* outI = out + (size_t)T * (EXP + 2);
        if (flags & 1) {
            outW[(size_t)r * 2 + 0] = v1;
            outW[(size_t)r * 2 + 1] = v2;
        }
        if (flags & 2) {
            outI[(size_t)r * 2 + 0] = (float)i1;
            outI[(size_t)r * 2 + 1] = (float)i2;
        }
    }
}

extern "C" void kernel_launch(void* const* d_in, const int* in_sizes, int n_in,
                              void* d_out, int out_size) {
    const float* x = (const float*)d_in[0];
    const float* W = (const float*)d_in[1];

    int T = in_sizes[0] / H;  // 16384

    int dev = 0;
    cudaGetDevice(&dev);
    int sm = 148;
    cudaDeviceGetAttribute(&sm, cudaDevAttrMultiProcessorCount, dev);

    int flags = 0;
    if (out_size >= T * (EXP + 2)) flags |= 1;
    if (out_size >= T * (EXP + 4)) flags |= 2;

    router_p1<<<sm, 512>>>(x, W, T);
    int warps_needed = T;                     // one warp per row
    int blocks2 = (warps_needed * 32 + 255) / 256;
    router_p2<<<blocks2, 256>>>(T, (float*)d_out, flags);
}

// round 3
// speedup vs baseline: 1.3533x; 1.0222x over previous
#include <cuda_runtime.h>

#define H     4096
#define TMAX  16384
#define EXP   8
#define FULLM 0xFFFFFFFFu

// Phase-1 partials: [row][32 warps][8 experts] = 16 MB
__device__ float g_scratch[(size_t)TMAX * 32 * EXP];

typedef unsigned long long u64;

__device__ __forceinline__ u64 fma2(u64 a, u64 b, u64 c) {
    u64 d; asm("fma.rn.f32x2 %0,%1,%2,%3;" : "=l"(d) : "l"(a), "l"(b), "l"(c)); return d;
}
__device__ __forceinline__ u64 mul2(u64 a, u64 b) {
    u64 d; asm("mul.rn.f32x2 %0,%1,%2;" : "=l"(d) : "l"(a), "l"(b)); return d;
}
__device__ __forceinline__ float hadd2(u64 v) {
    float lo = __uint_as_float((unsigned)v);
    float hi = __uint_as_float((unsigned)(v >> 32));
    return lo + hi;
}

// Reduce 8 per-lane values across 32 lanes (vector-halving butterfly, 9 shfls).
// Result: lane 4e holds the sum for expert e.
__device__ __forceinline__ float reduce8(float a[8]) {
    const int lane = threadIdx.x & 31;
    {
        bool hi = (lane & 16) != 0;
        float s0 = hi ? a[0] : a[4];
        float s1 = hi ? a[1] : a[5];
        float s2 = hi ? a[2] : a[6];
        float s3 = hi ? a[3] : a[7];
        s0 = __shfl_xor_sync(FULLM, s0, 16);
        s1 = __shfl_xor_sync(FULLM, s1, 16);
        s2 = __shfl_xor_sync(FULLM, s2, 16);
        s3 = __shfl_xor_sync(FULLM, s3, 16);
        a[0] = (hi ? a[4] : a[0]) + s0;
        a[1] = (hi ? a[5] : a[1]) + s1;
        a[2] = (hi ? a[6] : a[2]) + s2;
        a[3] = (hi ? a[7] : a[3]) + s3;
    }
    {
        bool hi = (lane & 8) != 0;
        float s0 = hi ? a[0] : a[2];
        float s1 = hi ? a[1] : a[3];
        s0 = __shfl_xor_sync(FULLM, s0, 8);
        s1 = __shfl_xor_sync(FULLM, s1, 8);
        a[0] = (hi ? a[2] : a[0]) + s0;
        a[1] = (hi ? a[3] : a[1]) + s1;
    }
    {
        bool hi = (lane & 4) != 0;
        float s0 = hi ? a[0] : a[1];
        s0 = __shfl_xor_sync(FULLM, s0, 4);
        a[0] = (hi ? a[1] : a[0]) + s0;
    }
    float v = a[0];
    v += __shfl_xor_sync(FULLM, v, 2);
    v += __shfl_xor_sync(FULLM, v, 1);
    return v;
}

// ── Phase 1: streaming GEMV partials. 1024 threads; thread owns 4 consecutive k.
//   8 warps/SMSP for latency hiding; no block-level sync.
__global__ void __launch_bounds__(1024, 1)
router_p1(const float* __restrict__ x, const float* __restrict__ W, int T) {
    const int tid  = threadIdx.x;
    const int lane = tid & 31;
    const int warp = tid >> 5;
    const int nb   = gridDim.x;

    // W slice in registers: 8 experts x 1 float4 (= 2 packed f32x2) = 32 regs
    u64 wx[EXP], wy[EXP];
#pragma unroll
    for (int e = 0; e < EXP; e++) {
        ulonglong2 t = reinterpret_cast<const ulonglong2*>(W + e * H)[tid];
        wx[e] = t.x; wy[e] = t.y;
    }

    const ulonglong2* x2 = reinterpret_cast<const ulonglong2*>(x);
    const int stride2 = H / 4;  // 1024 ulonglong2 per row

    // software pipeline: cur, next, loading
    int r = blockIdx.x;
    ulonglong2 cur = make_ulonglong2(0ull, 0ull), nxt = cur;
    if (r < T)      cur = x2[(size_t)r * stride2 + tid];
    if (r + nb < T) nxt = x2[(size_t)(r + nb) * stride2 + tid];

    for (; r < T; r += nb) {
        ulonglong2 pf = nxt;
        int rp = r + 2 * nb;
        if (rp < T) pf = x2[(size_t)rp * stride2 + tid];

        float a8[EXP];
#pragma unroll
        for (int e = 0; e < EXP; e++) {
            u64 acc = mul2(cur.y, wy[e]);
            acc = fma2(cur.x, wx[e], acc);
            a8[e] = hadd2(acc);
        }

        float v = reduce8(a8);
        if ((lane & 3) == 0)
            g_scratch[((size_t)r * 32 + warp) * EXP + (lane >> 2)] = v;

        cur = nxt;
        nxt = pf;
    }
}

// ── Phase 2: one warp per row (grid-stride). Lane l owns partial slot l
//   (2x LDG.128). Reduce across lanes, softmax, top-2, write outputs.
__global__ void __launch_bounds__(256)
router_p2(int T, float* __restrict__ out, int flags) {
    const int lane   = threadIdx.x & 31;
    const int warpId = (blockIdx.x * 256 + threadIdx.x) >> 5;
    const int nwarps = (gridDim.x * 256) >> 5;

    float* outW = out + (size_t)T * EXP;
    float* outI = out + (size_t)T * (EXP + 2);

    int r = warpId;
    float4 u = make_float4(0.f, 0.f, 0.f, 0.f), v = u;
    if (r < T) {
        const float4* p = reinterpret_cast<const float4*>(g_scratch + ((size_t)r * 32 + lane) * EXP);
        u = p[0]; v = p[1];
    }

    for (; r < T; r += nwarps) {
        // prefetch next row's partials
        float4 un = u, vn = v;
        int rn = r + nwarps;
        if (rn < T) {
            const float4* p = reinterpret_cast<const float4*>(g_scratch + ((size_t)rn * 32 + lane) * EXP);
            un = p[0]; vn = p[1];
        }

        float a[EXP] = {u.x, u.y, u.z, u.w, v.x, v.y, v.z, v.w};
        float t = reduce8(a);  // lane 4e -> logit[e]

        // softmax over the 8 distributed logits (orbit of lane bits {16,8,4})
        float m = t;
        m = fmaxf(m, __shfl_xor_sync(FULLM, m, 16));
        m = fmaxf(m, __shfl_xor_sync(FULLM, m, 8));
        m = fmaxf(m, __shfl_xor_sync(FULLM, m, 4));
        float p = __expf(t - m);
        float s = p;
        s += __shfl_xor_sync(FULLM, s, 16);
        s += __shfl_xor_sync(FULLM, s, 8);
        s += __shfl_xor_sync(FULLM, s, 4);
        float sc = __fdividef(p, s);

        int e = ((lane >> 4) & 1) * 4 + ((lane >> 3) & 1) * 2 + ((lane >> 2) & 1);
        if ((lane & 3) == 0)
            out[(size_t)r * EXP + e] = sc;

        // top-1 (ties -> lower index, matching lax.top_k)
        float v1 = sc; int i1 = e;
#pragma unroll
        for (int d = 16; d >= 4; d >>= 1) {
            float ov = __shfl_xor_sync(FULLM, v1, d);
            int   oi = __shfl_xor_sync(FULLM, i1, d);
            if (ov > v1 || (ov == v1 && oi < i1)) { v1 = ov; i1 = oi; }
        }
        // top-2: mask winner (softmax scores > 0)
        float v2 = (e == i1) ? -1.0f : sc; int i2 = e;
#pragma unroll
        for (int d = 16; d >= 4; d >>= 1) {
            float ov = __shfl_xor_sync(FULLM, v2, d);
            int   oi = __shfl_xor_sync(FULLM, i2, d);
            if (ov > v2 || (ov == v2 && oi < i2)) { v2 = ov; i2 = oi; }
        }

        if (lane == 0) {
            if (flags & 1) {
                outW[(size_t)r * 2 + 0] = v1;
                outW[(size_t)r * 2 + 1] = v2;
            }
            if (flags & 2) {
                outI[(size_t)r * 2 + 0] = (float)i1;
                outI[(size_t)r * 2 + 1] = (float)i2;
            }
        }

        u = un; v = vn;
    }
}

extern "C" void kernel_launch(void* const* d_in, const int* in_sizes, int n_in,
                              void* d_out, int out_size) {
    const float* x = (const float*)d_in[0];
    const float* W = (const float*)d_in[1];

    int T = in_sizes[0] / H;  // 16384

    int dev = 0;
    cudaGetDevice(&dev);
    int sm = 148;
    cudaDeviceGetAttribute(&sm, cudaDevAttrMultiProcessorCount, dev);

    int flags = 0;
    if (out_size >= T * (EXP + 2)) flags |= 1;
    if (out_size >= T * (EXP + 4)) flags |= 2;

    router_p1<<<sm, 1024>>>(x, W, T);
    router_p2<<<2 * sm, 256>>>(T, (float*)d_out, flags);
}

// round 4
// speedup vs baseline: 1.7746x; 1.3113x over previous
#include <cuda_runtime.h>

#define H      4096
#define TMAX   16384
#define EXP    8
#define FULLM  0xFFFFFFFFu
#define STAGES 6
#define ROWB   16384            // bytes per row stage in smem (1024 threads * 16B)

// Phase-1 partials: [row][32 warps][8 experts] = 16 MB
__device__ float g_scratch[(size_t)TMAX * 32 * EXP];

typedef unsigned long long u64;

__device__ __forceinline__ u64 fma2(u64 a, u64 b, u64 c) {
    u64 d; asm("fma.rn.f32x2 %0,%1,%2,%3;" : "=l"(d) : "l"(a), "l"(b), "l"(c)); return d;
}
__device__ __forceinline__ u64 mul2(u64 a, u64 b) {
    u64 d; asm("mul.rn.f32x2 %0,%1,%2;" : "=l"(d) : "l"(a), "l"(b)); return d;
}
__device__ __forceinline__ float hadd2(u64 v) {
    float lo = __uint_as_float((unsigned)v);
    float hi = __uint_as_float((unsigned)(v >> 32));
    return lo + hi;
}

// Reduce 8 per-lane values across 32 lanes (vector-halving butterfly, 9 shfls).
// Result: lane 4e holds the sum for expert e.
__device__ __forceinline__ float reduce8(float a[8]) {
    const int lane = threadIdx.x & 31;
    {
        bool hi = (lane & 16) != 0;
        float s0 = hi ? a[0] : a[4];
        float s1 = hi ? a[1] : a[5];
        float s2 = hi ? a[2] : a[6];
        float s3 = hi ? a[3] : a[7];
        s0 = __shfl_xor_sync(FULLM, s0, 16);
        s1 = __shfl_xor_sync(FULLM, s1, 16);
        s2 = __shfl_xor_sync(FULLM, s2, 16);
        s3 = __shfl_xor_sync(FULLM, s3, 16);
        a[0] = (hi ? a[4] : a[0]) + s0;
        a[1] = (hi ? a[5] : a[1]) + s1;
        a[2] = (hi ? a[6] : a[2]) + s2;
        a[3] = (hi ? a[7] : a[3]) + s3;
    }
    {
        bool hi = (lane & 8) != 0;
        float s0 = hi ? a[0] : a[2];
        float s1 = hi ? a[1] : a[3];
        s0 = __shfl_xor_sync(FULLM, s0, 8);
        s1 = __shfl_xor_sync(FULLM, s1, 8);
        a[0] = (hi ? a[2] : a[0]) + s0;
        a[1] = (hi ? a[3] : a[1]) + s1;
    }
    {
        bool hi = (lane & 4) != 0;
        float s0 = hi ? a[0] : a[1];
        s0 = __shfl_xor_sync(FULLM, s0, 4);
        a[0] = (hi ? a[1] : a[0]) + s0;
    }
    float v = a[0];
    v += __shfl_xor_sync(FULLM, v, 2);
    v += __shfl_xor_sync(FULLM, v, 1);
    return v;
}

__device__ __forceinline__ void cp16(unsigned saddr, const void* gaddr) {
    asm volatile("cp.async.cg.shared.global [%0], [%1], 16;" :: "r"(saddr), "l"(gaddr));
}
__device__ __forceinline__ void cp_commit() {
    asm volatile("cp.async.commit_group;" ::: "memory");
}
__device__ __forceinline__ void cp_wait5() {
    asm volatile("cp.async.wait_group 5;" ::: "memory");
}

// ── Phase 1: streaming GEMV partials.
//   1024 threads; thread owns 4 consecutive k (16B per row).
//   Per-thread 6-deep cp.async pipeline into a PRIVATE smem slot —
//   each thread consumes only bytes it copied, so no block/warp sync at all.
__global__ void __launch_bounds__(1024, 1)
router_p1(const float* __restrict__ x, const float* __restrict__ W, int T) {
    extern __shared__ char smem[];   // STAGES * 16KB = 96KB

    const int tid  = threadIdx.x;
    const int lane = tid & 31;
    const int warp = tid >> 5;
    const int nb   = gridDim.x;

    // W slice in registers: 8 experts x 1 float4 (= 2 packed f32x2) = 32 regs
    u64 wx[EXP], wy[EXP];
#pragma unroll
    for (int e = 0; e < EXP; e++) {
        ulonglong2 t = reinterpret_cast<const ulonglong2*>(W + e * H)[tid];
        wx[e] = t.x; wy[e] = t.y;
    }

    unsigned sbase;
    asm("{ .reg .u64 t; cvta.to.shared.u64 t, %1; cvt.u32.u64 %0, t; }"
        : "=r"(sbase) : "l"(smem + tid * 16));

    const char* xg = reinterpret_cast<const char*>(x);
    const size_t rowBytes = (size_t)H * 4;
    const size_t myOff = (size_t)tid * 16;

    const int r0 = blockIdx.x;

    // prologue: fill STAGES groups (one commit per stage, even if predicated off)
#pragma unroll
    for (int s = 0; s < STAGES; s++) {
        int r = r0 + s * nb;
        if (r < T) cp16(sbase + s * ROWB, xg + (size_t)r * rowBytes + myOff);
        cp_commit();
    }

    int s = 0;
    for (int r = r0; r < T; r += nb) {
        cp_wait5();  // oldest stage ready (<=5 groups pending)

        ulonglong2 cur = *reinterpret_cast<const ulonglong2*>(smem + s * ROWB + tid * 16);

        float a8[EXP];
#pragma unroll
        for (int e = 0; e < EXP; e++) {
            u64 acc = mul2(cur.y, wy[e]);
            acc = fma2(cur.x, wx[e], acc);
            a8[e] = hadd2(acc);
        }

        float v = reduce8(a8);
        if ((lane & 3) == 0)
            g_scratch[((size_t)r * 32 + warp) * EXP + (lane >> 2)] = v;

        // refill this stage with row r + STAGES*nb
        int rp = r + STAGES * nb;
        if (rp < T) cp16(sbase + s * ROWB, xg + (size_t)rp * rowBytes + myOff);
        cp_commit();

        s = (s == STAGES - 1) ? 0 : s + 1;
    }
}

// ── Phase 2: one warp per row, one row per warp (no grid-stride).
//   Lane l owns partial slot l (2x LDG.128, 1KB/row coalesced).
__global__ void __launch_bounds__(256)
router_p2(int T, float* __restrict__ out, int flags) {
    const int lane = threadIdx.x & 31;
    const int r    = (blockIdx.x * 256 + threadIdx.x) >> 5;
    if (r >= T) return;

    const float4* p = reinterpret_cast<const float4*>(g_scratch + ((size_t)r * 32 + lane) * EXP);
    float4 u = p[0], v = p[1];

    float a[EXP] = {u.x, u.y, u.z, u.w, v.x, v.y, v.z, v.w};
    float t = reduce8(a);  // lane 4e -> logit[e]

    // softmax over the 8 distributed logits (orbit of lane bits {16,8,4})
    float m = t;
    m = fmaxf(m, __shfl_xor_sync(FULLM, m, 16));
    m = fmaxf(m, __shfl_xor_sync(FULLM, m, 8));
    m = fmaxf(m, __shfl_xor_sync(FULLM, m, 4));
    float pz = __expf(t - m);
    float sden = pz;
    sden += __shfl_xor_sync(FULLM, sden, 16);
    sden += __shfl_xor_sync(FULLM, sden, 8);
    sden += __shfl_xor_sync(FULLM, sden, 4);
    float sc = __fdividef(pz, sden);

    int e = ((lane >> 4) & 1) * 4 + ((lane >> 3) & 1) * 2 + ((lane >> 2) & 1);
    if ((lane & 3) == 0)
        out[(size_t)r * EXP + e] = sc;

    // top-1 (ties -> lower index, matching lax.top_k)
    float v1 = sc; int i1 = e;
#pragma unroll
    for (int d = 16; d >= 4; d >>= 1) {
        float ov = __shfl_xor_sync(FULLM, v1, d);
        int   oi = __shfl_xor_sync(FULLM, i1, d);
        if (ov > v1 || (ov == v1 && oi < i1)) { v1 = ov; i1 = oi; }
    }
    // top-2: mask winner (softmax scores > 0)
    float v2 = (e == i1) ? -1.0f : sc; int i2 = e;
#pragma unroll
    for (int d = 16; d >= 4; d >>= 1) {
        float ov = __shfl_xor_sync(FULLM, v2, d);
        int   oi = __shfl_xor_sync(FULLM, i2, d);
        if (ov > v2 || (ov == v2 && oi < i2)) { v2 = ov; i2 = oi; }
    }

    if (lane == 0) {
        float* outW = out + (size_t)T * EXP;
        float* outI = out + (size_t)T * (EXP + 2);
        if (flags & 1) {
            outW[(size_t)r * 2 + 0] = v1;
            outW[(size_t)r * 2 + 1] = v2;
        }
        if (flags & 2) {
            outI[(size_t)r * 2 + 0] = (float)i1;
            outI[(size_t)r * 2 + 1] = (float)i2;
        }
    }
}

extern "C" void kernel_launch(void* const* d_in, const int* in_sizes, int n_in,
                              void* d_out, int out_size) {
    const float* x = (const float*)d_in[0];
    const float* W = (const float*)d_in[1];

    int T = in_sizes[0] / H;  // 16384

    int dev = 0;
    cudaGetDevice(&dev);
    int sm = 148;
    cudaDeviceGetAttribute(&sm, cudaDevAttrMultiProcessorCount, dev);

    int flags = 0;
    if (out_size >= T * (EXP + 2)) flags |= 1;
    if (out_size >= T * (EXP + 4)) flags |= 2;

    static int smemSet = 0;
    if (!smemSet) {
        cudaFuncSetAttribute(router_p1, cudaFuncAttributeMaxDynamicSharedMemorySize,
                             STAGES * ROWB);
        smemSet = 1;
    }

    router_p1<<<sm, 1024, STAGES * ROWB>>>(x, W, T);
    int blocks2 = (T * 32 + 255) / 256;   // one warp per row
    router_p2<<<blocks2, 256>>>(T, (float*)d_out, flags);
}